// round 2
// baseline (speedup 1.0000x reference)
#include <cuda_runtime.h>
#include <math.h>

// Problem constants
#define N_SAMP 2048
#define D_DIM  512
#define C_CLS  10000
#define KSUB   3
#define CK     30000          // C_CLS * KSUB
#define NTILES 250            // CK / 120
#define ARC_S  30.0f
#define COS_M  0.9210609940028851f   // cos(0.4)
#define SIN_M  0.3894183423086505f   // sin(0.4)
#define TRIP_M 0.3f

// ---------------- scratch (static device globals: no runtime allocation) ----------------
__device__ float  g_e[N_SAMP * D_DIM];          // normalized embeddings   4 MB
__device__ float  g_invw[CK];                   // 1/||w_col||             120 KB
__device__ float  g_arc_m[N_SAMP * NTILES];     // per-(row,tile) lse max  2 MB
__device__ float  g_arc_s[N_SAMP * NTILES];     // per-(row,tile) lse sum  2 MB
__device__ float  g_lab[N_SAMP];                // label logit per row
__device__ float  g_sim[N_SAMP * N_SAMP];       // e @ e^T                 16.8 MB
__device__ double g_arc_sum;
__device__ double g_tl_sum;
__device__ double g_center_sum;
__device__ int    g_nnz;

// ---------------- init: zero accumulators every launch (graph replays!) ----------------
__global__ void k_init() {
    g_arc_sum = 0.0; g_tl_sum = 0.0; g_center_sum = 0.0; g_nnz = 0;
}

// ---------------- normalize embeddings: one block per row ----------------
__global__ void k_norm_emb(const float* __restrict__ emb) {
    int row = blockIdx.x;
    int tid = threadIdx.x;
    const float* src = emb + row * D_DIM;
    float s = 0.f;
    for (int d = tid; d < D_DIM; d += blockDim.x) { float v = src[d]; s += v * v; }
    __shared__ float red[256];
    red[tid] = s; __syncthreads();
    for (int st = 128; st > 0; st >>= 1) {
        if (tid < st) red[tid] += red[tid + st];
        __syncthreads();
    }
    float inv = 1.f / fmaxf(sqrtf(red[0]), 1e-12f);
    for (int d = tid; d < D_DIM; d += blockDim.x)
        g_e[row * D_DIM + d] = src[d] * inv;
}

// ---------------- arc_weight column inverse norms ----------------
__global__ void k_wnorm(const float* __restrict__ W) {
    int j = blockIdx.x * blockDim.x + threadIdx.x;
    if (j >= CK) return;
    float s = 0.f;
    #pragma unroll 8
    for (int k = 0; k < D_DIM; k++) {
        float v = W[k * CK + j];
        s += v * v;
    }
    g_invw[j] = 1.f / fmaxf(sqrtf(s), 1e-12f);
}

// ============================================================================
// Fused GEMM + subcenter-max + ArcFace margin + streaming logsumexp partials
// Tile: 128 rows x 120 cols (= 40 classes), BK=8, 320 threads, 8x6 per thread.
// 30000 / 120 = 250 tiles exactly -> no column bounds checks.
// ============================================================================
#define BM 128
#define BN 120
#define BK 8
#define TM 8
#define TN 6
#define NT 320   // 16 row-threads x 20 col-threads

__global__ __launch_bounds__(NT) void k_gemm_arc(const float* __restrict__ W,
                                                 const int* __restrict__ labels) {
    __shared__ float As[BK][BM];
    __shared__ float Bs[BK][BN];
    __shared__ float part_m[BM][20];
    __shared__ float part_s[BM][20];

    const int tid  = threadIdx.x;
    const int trow = tid / 20;       // 0..15
    const int tcol = tid % 20;       // 0..19
    const int rowA = blockIdx.y * BM;
    const int colB = blockIdx.x * BN;

    float acc[TM][TN];
    #pragma unroll
    for (int m = 0; m < TM; m++)
        #pragma unroll
        for (int n = 0; n < TN; n++) acc[m][n] = 0.f;

    const bool doA = tid < 256;      // 256 float4 for A tile
    const bool doB = tid < 240;      // 240 float4 for B tile
    const int aRow = tid >> 1;             // 0..127
    const int aCol = (tid & 1) << 2;       // 0 or 4
    const int bRow = tid / 30;             // 0..7
    const int bCol = (tid % 30) << 2;      // 0..116

    for (int k0 = 0; k0 < D_DIM; k0 += BK) {
        if (doA) {
            float4 a = *(const float4*)(&g_e[(rowA + aRow) * D_DIM + k0 + aCol]);
            As[aCol + 0][aRow] = a.x; As[aCol + 1][aRow] = a.y;
            As[aCol + 2][aRow] = a.z; As[aCol + 3][aRow] = a.w;
        }
        if (doB) {
            float4 b = *(const float4*)(&W[(k0 + bRow) * CK + colB + bCol]);
            Bs[bRow][bCol + 0] = b.x; Bs[bRow][bCol + 1] = b.y;
            Bs[bRow][bCol + 2] = b.z; Bs[bRow][bCol + 3] = b.w;
        }
        __syncthreads();

        #pragma unroll
        for (int k = 0; k < BK; k++) {
            float4 a0 = *(const float4*)(&As[k][trow * TM]);
            float4 a1 = *(const float4*)(&As[k][trow * TM + 4]);
            float2 b01 = *(const float2*)(&Bs[k][tcol * TN]);
            float2 b23 = *(const float2*)(&Bs[k][tcol * TN + 2]);
            float2 b45 = *(const float2*)(&Bs[k][tcol * TN + 4]);
            float ar[TM] = {a0.x, a0.y, a0.z, a0.w, a1.x, a1.y, a1.z, a1.w};
            float br[TN] = {b01.x, b01.y, b23.x, b23.y, b45.x, b45.y};
            #pragma unroll
            for (int m = 0; m < TM; m++)
                #pragma unroll
                for (int n = 0; n < TN; n++)
                    acc[m][n] += ar[m] * br[n];
        }
        __syncthreads();
    }

    // ---- epilogue: 2 classes per thread (6 cols / 3 subcenters) ----
    float iw[TN];
    #pragma unroll
    for (int n = 0; n < TN; n++) iw[n] = g_invw[colB + tcol * TN + n];
    const int c0 = (colB + tcol * TN) / 3;   // first of this thread's 2 classes

    #pragma unroll
    for (int m = 0; m < TM; m++) {
        int gi  = rowA + trow * TM + m;
        int lab = labels[gi];

        float lg[2];
        #pragma unroll
        for (int g = 0; g < 2; g++) {
            float cm = fmaxf(fmaxf(acc[m][3*g] * iw[3*g], acc[m][3*g+1] * iw[3*g+1]),
                             acc[m][3*g+2] * iw[3*g+2]);
            int c = c0 + g;
            float logit;
            if (c == lab) {
                float cc = fminf(fmaxf(cm, -1.f + 1e-7f), 1.f - 1e-7f);
                float sn = sqrtf(fmaxf(1.f - cc * cc, 0.f));
                logit = ARC_S * (cc * COS_M - sn * SIN_M);
                g_lab[gi] = logit;
            } else {
                logit = ARC_S * cm;
            }
            lg[g] = logit;
        }
        float mm = fmaxf(lg[0], lg[1]);
        float ss = expf(lg[0] - mm) + expf(lg[1] - mm);
        int r = trow * TM + m;
        part_m[r][tcol] = mm;
        part_s[r][tcol] = ss;
    }
    __syncthreads();

    // ---- block reduce: thread r (0..127) merges 20 partials for its row ----
    if (tid < BM) {
        float M = part_m[tid][0], S = part_s[tid][0];
        #pragma unroll
        for (int t = 1; t < 20; t++) {
            float mt = part_m[tid][t], st = part_s[tid][t];
            if (mt > M) { S = S * expf(M - mt) + st; M = mt; }
            else        { S += st * expf(mt - M); }
        }
        int gi = rowA + tid;
        g_arc_m[gi * NTILES + blockIdx.x] = M;
        g_arc_s[gi * NTILES + blockIdx.x] = S;
    }
}

// ---------------- arc reduce: one block per row, merge 250 partials ----------------
__global__ void k_arc_reduce() {
    int row = blockIdx.x;
    int tid = threadIdx.x;
    float M = -1e30f, S = 0.f;
    if (tid < NTILES) {
        M = g_arc_m[row * NTILES + tid];
        S = g_arc_s[row * NTILES + tid];
    }
    __shared__ float sm[256], ss[256];
    sm[tid] = M; ss[tid] = S;
    __syncthreads();
    for (int st = 128; st > 0; st >>= 1) {
        if (tid < st) {
            float m2 = sm[tid + st], s2 = ss[tid + st];
            float m1 = sm[tid],      s1 = ss[tid];
            if (m2 > m1) { ss[tid] = s1 * expf(m1 - m2) + s2; sm[tid] = m2; }
            else         { ss[tid] = s1 + s2 * expf(m2 - m1); }
        }
        __syncthreads();
    }
    if (tid == 0) {
        float lse = sm[0] + logf(ss[0]);
        atomicAdd(&g_arc_sum, (double)(lse - g_lab[row]));
    }
}

// ============================================================================
// sim GEMM (NT, 2048x2048): classic 128x128x8, 8x8 per thread, 256 threads
// ============================================================================
#define SBM 128
#define SBN 128

__global__ __launch_bounds__(256, 2) void k_gemm_sim() {
    __shared__ float As[BK][SBM];
    __shared__ float Bs[BK][SBN];
    const int tid  = threadIdx.x;
    const int trow = tid >> 4;
    const int tcol = tid & 15;
    const int rowA = blockIdx.y * SBM;
    const int colB = blockIdx.x * SBN;

    const int aRow = tid >> 1;
    const int aCol = (tid & 1) << 2;

    float acc[8][8];
    #pragma unroll
    for (int m = 0; m < 8; m++)
        #pragma unroll
        for (int n = 0; n < 8; n++) acc[m][n] = 0.f;

    for (int k0 = 0; k0 < D_DIM; k0 += BK) {
        float4 a = *(const float4*)(&g_e[(rowA + aRow) * D_DIM + k0 + aCol]);
        As[aCol + 0][aRow] = a.x; As[aCol + 1][aRow] = a.y;
        As[aCol + 2][aRow] = a.z; As[aCol + 3][aRow] = a.w;

        float4 b = *(const float4*)(&g_e[(colB + aRow) * D_DIM + k0 + aCol]);
        Bs[aCol + 0][aRow] = b.x; Bs[aCol + 1][aRow] = b.y;
        Bs[aCol + 2][aRow] = b.z; Bs[aCol + 3][aRow] = b.w;
        __syncthreads();

        #pragma unroll
        for (int k = 0; k < BK; k++) {
            float4 a0 = *(const float4*)(&As[k][trow * 8]);
            float4 a1 = *(const float4*)(&As[k][trow * 8 + 4]);
            float4 b0 = *(const float4*)(&Bs[k][tcol * 8]);
            float4 b1 = *(const float4*)(&Bs[k][tcol * 8 + 4]);
            float ar[8] = {a0.x, a0.y, a0.z, a0.w, a1.x, a1.y, a1.z, a1.w};
            float br[8] = {b0.x, b0.y, b0.z, b0.w, b1.x, b1.y, b1.z, b1.w};
            #pragma unroll
            for (int m = 0; m < 8; m++)
                #pragma unroll
                for (int n = 0; n < 8; n++)
                    acc[m][n] += ar[m] * br[n];
        }
        __syncthreads();
    }

    #pragma unroll
    for (int m = 0; m < 8; m++) {
        int gi = rowA + trow * 8 + m;
        #pragma unroll
        for (int n = 0; n < 8; n++)
            g_sim[gi * N_SAMP + colB + tcol * 8 + n] = acc[m][n];
    }
}

// ---------------- batch-hard triplet ----------------
__global__ void k_triplet(const int* __restrict__ labels) {
    __shared__ int slab[N_SAMP];
    int row = blockIdx.x;
    int tid = threadIdx.x;
    for (int j = tid; j < N_SAMP; j += blockDim.x) slab[j] = labels[j];
    __syncthreads();

    int myLab = slab[row];
    float dap = -1.f, dan = 3.f;
    const float* srow = &g_sim[row * N_SAMP];
    for (int j = tid; j < N_SAMP; j += blockDim.x) {
        float sim  = srow[j];
        float dist = sqrtf(fmaxf(2.f - 2.f * sim, 0.f));
        if (slab[j] == myLab) {
            if (j != row) dap = fmaxf(dap, dist);
        } else {
            dan = fminf(dan, dist);
        }
    }

    __shared__ float smax[256], smin[256];
    smax[tid] = dap; smin[tid] = dan;
    __syncthreads();
    for (int st = 128; st > 0; st >>= 1) {
        if (tid < st) {
            smax[tid] = fmaxf(smax[tid], smax[tid + st]);
            smin[tid] = fminf(smin[tid], smin[tid + st]);
        }
        __syncthreads();
    }
    if (tid == 0) {
        float Dap = smax[0], Dan = smin[0];
        bool valid = (Dap >= 0.f) && (Dan < 2.5f);   // has positive && has negative
        float tl = valid ? fmaxf(Dap - Dan + TRIP_M, 0.f) : 0.f;
        if (tl > 0.f) {
            atomicAdd(&g_tl_sum, (double)tl);
            atomicAdd(&g_nnz, 1);
        }
    }
}

// ---------------- center loss ----------------
__global__ void k_center(const int* __restrict__ labels, const float* __restrict__ centers) {
    int row = blockIdx.x;
    int tid = threadIdx.x;
    int lab = labels[row];
    const float* c = centers + lab * D_DIM;
    const float* e = g_e + row * D_DIM;
    float s = 0.f;
    for (int d = tid; d < D_DIM; d += blockDim.x) {
        float diff = e[d] - c[d];
        s += diff * diff;
    }
    __shared__ float red[256];
    red[tid] = s; __syncthreads();
    for (int st = 128; st > 0; st >>= 1) {
        if (tid < st) red[tid] += red[tid + st];
        __syncthreads();
    }
    if (tid == 0) atomicAdd(&g_center_sum, (double)red[0]);
}

// ---------------- finalize ----------------
__global__ void k_final(float* __restrict__ out) {
    double arc  = g_arc_sum / (double)N_SAMP;
    int    nnz  = g_nnz > 1 ? g_nnz : 1;
    double trip = g_tl_sum / (double)nnz;
    double cen  = g_center_sum / (double)N_SAMP;
    out[0] = (float)(arc + 0.5 * trip + 0.01 * cen);
}

// ---------------- launch ----------------
extern "C" void kernel_launch(void* const* d_in, const int* in_sizes, int n_in,
                              void* d_out, int out_size) {
    const float* emb     = (const float*)d_in[0];
    const int*   labels  = (const int*)  d_in[1];
    const float* W       = (const float*)d_in[2];
    const float* centers = (const float*)d_in[3];
    float* out = (float*)d_out;

    k_init<<<1, 1>>>();
    k_norm_emb<<<N_SAMP, 256>>>(emb);
    k_wnorm<<<(CK + 255) / 256, 256>>>(W);

    dim3 garc(NTILES, N_SAMP / BM);               // (250, 16)
    k_gemm_arc<<<garc, NT>>>(W, labels);
    k_arc_reduce<<<N_SAMP, 256>>>();

    dim3 gsim(N_SAMP / SBN, N_SAMP / SBM);        // (16, 16)
    k_gemm_sim<<<gsim, 256>>>();
    k_triplet<<<N_SAMP, 256>>>(labels);

    k_center<<<N_SAMP, 256>>>(labels, centers);
    k_final<<<1, 1>>>(out);
}

// round 4
// speedup vs baseline: 2.3293x; 2.3293x over previous
#include <cuda_runtime.h>
#include <cuda_bf16.h>
#include <math.h>
#include <stdint.h>

// ---------------- problem constants ----------------
#define N_SAMP 2048
#define D_DIM  512
#define C_CLS  10000
#define CK     30000
#define CK_PAD 30720
#define ARC_S  30.0f
#define COS_M  0.9210609940028851f   // cos(0.4)
#define SIN_M  0.3894183423086505f   // sin(0.4)
#define TRIP_M 0.3f

#define ABN      96                  // arc tile N (32 classes)
#define NTILES_G 313                 // ceil(30000/96) -> cols 0..30047 (padded)

// ---------------- scratch ----------------
__device__ __align__(128) float         g_e[N_SAMP * D_DIM];
__device__ __align__(128) __nv_bfloat16 g_e_hi[N_SAMP * D_DIM];
__device__ __align__(128) __nv_bfloat16 g_e_lo[N_SAMP * D_DIM];
__device__ __align__(128) __nv_bfloat16 g_wt_hi[CK_PAD * D_DIM];  // zero-padded rows >= 30000
__device__ __align__(128) __nv_bfloat16 g_wt_lo[CK_PAD * D_DIM];
__device__ float  g_invw[CK];
__device__ float  g_arc_m[N_SAMP * NTILES_G];
__device__ float  g_arc_s[N_SAMP * NTILES_G];
__device__ float  g_lab[N_SAMP];
__device__ int    g_dap[N_SAMP];
__device__ int    g_dan[N_SAMP];
__device__ double g_arc_sum, g_tl_sum, g_center_sum;
__device__ int    g_nnz;

// ---------------- PTX helpers (all plain-sm_100-safe: sm_80-era) ----------------
__device__ __forceinline__ uint32_t smem_u32(const void* p) {
    uint32_t a;
    asm("{ .reg .u64 t; cvta.to.shared.u64 t, %1; cvt.u32.u64 %0, t; }" : "=r"(a) : "l"(p));
    return a;
}
__device__ __forceinline__ void cp16(uint32_t dst, const void* src) {
    asm volatile("cp.async.cg.shared.global [%0], [%1], 16;" :: "r"(dst), "l"(src) : "memory");
}
#define CP_COMMIT() asm volatile("cp.async.commit_group;" ::: "memory")
#define CP_WAIT1()  asm volatile("cp.async.wait_group 1;" ::: "memory")
#define CP_WAIT0()  asm volatile("cp.async.wait_group 0;" ::: "memory")

__device__ __forceinline__ void ldsm4(uint32_t* r, uint32_t addr) {
    asm volatile("ldmatrix.sync.aligned.m8n8.x4.shared.b16 {%0,%1,%2,%3}, [%4];"
        : "=r"(r[0]), "=r"(r[1]), "=r"(r[2]), "=r"(r[3]) : "r"(addr));
}
__device__ __forceinline__ void mma16816(float* d, const uint32_t* a, uint32_t b0, uint32_t b1) {
    asm volatile("mma.sync.aligned.m16n8k16.row.col.f32.bf16.bf16.f32 "
        "{%0,%1,%2,%3}, {%4,%5,%6,%7}, {%8,%9}, {%0,%1,%2,%3};"
        : "+f"(d[0]), "+f"(d[1]), "+f"(d[2]), "+f"(d[3])
        : "r"(a[0]), "r"(a[1]), "r"(a[2]), "r"(a[3]), "r"(b0), "r"(b1));
}

// streaming lse merge
__device__ __forceinline__ void lse_merge(float& M, float& S, float m2, float s2) {
    if (m2 > M) { S = S * expf(M - m2) + s2; M = m2; }
    else        { S += s2 * expf(m2 - M); }
}

// ---------------- prep kernels ----------------
__global__ void k_init() {
    int i = blockIdx.x * blockDim.x + threadIdx.x;
    if (i < N_SAMP) { g_dap[i] = __float_as_int(-1.0f); g_dan[i] = __float_as_int(3.0f); }
    if (i == 0) { g_arc_sum = 0.0; g_tl_sum = 0.0; g_center_sum = 0.0; g_nnz = 0; }
}

__global__ void k_norm_emb(const float* __restrict__ emb) {
    int row = blockIdx.x, tid = threadIdx.x;
    const float* src = emb + row * D_DIM;
    float s = 0.f;
    for (int d = tid; d < D_DIM; d += 256) { float v = src[d]; s += v * v; }
    __shared__ float red[256];
    red[tid] = s; __syncthreads();
    for (int st = 128; st > 0; st >>= 1) { if (tid < st) red[tid] += red[tid + st]; __syncthreads(); }
    float inv = 1.f / fmaxf(sqrtf(red[0]), 1e-12f);
    for (int d = tid; d < D_DIM; d += 256) {
        float v = src[d] * inv;
        g_e[row * D_DIM + d] = v;
        __nv_bfloat16 h = __float2bfloat16(v);
        g_e_hi[row * D_DIM + d] = h;
        g_e_lo[row * D_DIM + d] = __float2bfloat16(v - __bfloat162float(h));
    }
}

__global__ void k_wnorm(const float* __restrict__ W) {
    int j = blockIdx.x * blockDim.x + threadIdx.x;
    if (j >= CK) return;
    float s = 0.f;
    #pragma unroll 8
    for (int k = 0; k < D_DIM; k++) { float v = W[k * CK + j]; s += v * v; }
    g_invw[j] = 1.f / fmaxf(sqrtf(s), 1e-12f);
}

// transpose + normalize + bf16 split:  Wt[j][k] = W[k][j] * invw[j]
__global__ void k_wtrans(const float* __restrict__ W) {
    __shared__ float tile[32][33];
    int j0 = blockIdx.x * 32, k0 = blockIdx.y * 32;
    int tx = threadIdx.x, ty = threadIdx.y;
    #pragma unroll
    for (int i = 0; i < 32; i += 8) {
        int k = k0 + ty + i, j = j0 + tx;
        tile[ty + i][tx] = (j < CK) ? W[k * CK + j] : 0.f;
    }
    __syncthreads();
    #pragma unroll
    for (int i = 0; i < 32; i += 8) {
        int j = j0 + ty + i, k = k0 + tx;
        if (j < CK) {
            float v = tile[tx][ty + i] * g_invw[j];
            __nv_bfloat16 h = __float2bfloat16(v);
            g_wt_hi[j * D_DIM + k] = h;
            g_wt_lo[j * D_DIM + k] = __float2bfloat16(v - __bfloat162float(h));
        }
    }
}

// ============================================================================
// arc GEMM: 128x96 tile, mma.sync bf16 3-pass, cp.async double-buffered.
// SMEM rows padded to 80B (odd*16B -> conflict-free ldmatrix).
// Stage: A_hi[128*80]=10240, A_lo=10240, B_hi[96*80]=7680, B_lo=7680 -> 35840
// ============================================================================
#define A_OFF_AL 10240
#define A_OFF_BH 20480
#define A_OFF_BL 28160
#define A_STG    35840
#define A_SMEM   (2 * A_STG)    // 71680; epilogue reuses (128*100*4 = 51200)

__device__ __forceinline__ void load_arc_stage(uint32_t st, int kc, int rowA, int colB, int tid) {
    int gk = kc * 32;
    #pragma unroll
    for (int i = 0; i < 2; i++) {
        int idx = tid + i * 256;
        int row = idx >> 2, c = idx & 3;
        uint32_t so = row * 80 + c * 16;
        cp16(st + so,            &g_e_hi[(rowA + row) * D_DIM + gk + c * 8]);
        cp16(st + A_OFF_AL + so, &g_e_lo[(rowA + row) * D_DIM + gk + c * 8]);
    }
    {
        int row = tid >> 2, c = tid & 3;
        uint32_t so = row * 80 + c * 16;
        cp16(st + A_OFF_BH + so, &g_wt_hi[(colB + row) * D_DIM + gk + c * 8]);
        cp16(st + A_OFF_BL + so, &g_wt_lo[(colB + row) * D_DIM + gk + c * 8]);
    }
    if (tid < 128) {
        int idx = tid + 256;
        int row = idx >> 2, c = idx & 3;
        uint32_t so = row * 80 + c * 16;
        cp16(st + A_OFF_BH + so, &g_wt_hi[(colB + row) * D_DIM + gk + c * 8]);
        cp16(st + A_OFF_BL + so, &g_wt_lo[(colB + row) * D_DIM + gk + c * 8]);
    }
}

__global__ void __launch_bounds__(256, 1) k_gemm_arc(const int* __restrict__ labels) {
    extern __shared__ char smem[];
    uint32_t sb = smem_u32(smem);
    int tid = threadIdx.x, wid = tid >> 5, lane = tid & 31;
    int warpM = wid & 3, warpN = wid >> 2;          // 4M x 2N
    int rowA = blockIdx.x * 128;
    int tileN = blockIdx.y;
    int colB = tileN * ABN;

    float acc[2][6][4];
    #pragma unroll
    for (int a = 0; a < 2; a++)
        #pragma unroll
        for (int b = 0; b < 6; b++)
            #pragma unroll
            for (int c = 0; c < 4; c++) acc[a][b][c] = 0.f;

    int lrow = lane & 15, lhalf = lane >> 4;
    uint32_t aoff[2], boff[3];
    #pragma unroll
    for (int mt = 0; mt < 2; mt++) aoff[mt] = (warpM * 32 + mt * 16 + lrow) * 80 + lhalf * 16;
    #pragma unroll
    for (int bt = 0; bt < 3; bt++) boff[bt] = (warpN * 48 + bt * 16 + lrow) * 80 + lhalf * 16;

    load_arc_stage(sb, 0, rowA, colB, tid); CP_COMMIT();
    load_arc_stage(sb + A_STG, 1, rowA, colB, tid); CP_COMMIT();

    for (int kc = 0; kc < 16; kc++) {
        if (kc < 15) CP_WAIT1(); else CP_WAIT0();
        __syncthreads();
        uint32_t st = sb + (kc & 1) * A_STG;
        #pragma unroll
        for (int ks = 0; ks < 2; ks++) {
            uint32_t ah[2][4], al[2][4], bh[3][4], bl[3][4];
            #pragma unroll
            for (int mt = 0; mt < 2; mt++) {
                ldsm4(ah[mt], st + aoff[mt] + ks * 32);
                ldsm4(al[mt], st + A_OFF_AL + aoff[mt] + ks * 32);
            }
            #pragma unroll
            for (int bt = 0; bt < 3; bt++) {
                ldsm4(bh[bt], st + A_OFF_BH + boff[bt] + ks * 32);
                ldsm4(bl[bt], st + A_OFF_BL + boff[bt] + ks * 32);
            }
            #pragma unroll
            for (int mt = 0; mt < 2; mt++)
                #pragma unroll
                for (int nt = 0; nt < 6; nt++) {
                    int bt = nt >> 1, sel = nt & 1;
                    mma16816(acc[mt][nt], ah[mt], bh[bt][sel], bh[bt][sel | 2]);
                    mma16816(acc[mt][nt], ah[mt], bl[bt][sel], bl[bt][sel | 2]);
                    mma16816(acc[mt][nt], al[mt], bh[bt][sel], bh[bt][sel | 2]);
                }
        }
        __syncthreads();
        if (kc + 2 < 16) { load_arc_stage(sb + (kc & 1) * A_STG, kc + 2, rowA, colB, tid); CP_COMMIT(); }
    }

    // ---- epilogue: accum -> smem (pitch 100 fp32), fused subcenter/margin/lse ----
    __syncthreads();
    float* se = (float*)smem;
    #pragma unroll
    for (int mt = 0; mt < 2; mt++) {
        int r = warpM * 32 + mt * 16 + (lane >> 2);
        #pragma unroll
        for (int nt = 0; nt < 6; nt++) {
            int c = warpN * 48 + nt * 8 + ((lane & 3) << 1);
            se[r * 100 + c]           = acc[mt][nt][0];
            se[r * 100 + c + 1]       = acc[mt][nt][1];
            se[(r + 8) * 100 + c]     = acc[mt][nt][2];
            se[(r + 8) * 100 + c + 1] = acc[mt][nt][3];
        }
    }
    __syncthreads();

    int r = tid >> 1, h = tid & 1;
    int gi = rowA + r;
    int lab = labels[gi];
    int cbase = tileN * 32 + h * 16;
    const float* row = se + r * 100 + h * 48;
    float M = -1e30f, S = 0.f;
    #pragma unroll
    for (int g = 0; g < 16; g++) {
        int c = cbase + g;
        if (c >= C_CLS) break;
        float cm = fmaxf(fmaxf(row[3*g], row[3*g+1]), row[3*g+2]);
        float logit;
        if (c == lab) {
            float cc = fminf(fmaxf(cm, -1.f + 1e-7f), 1.f - 1e-7f);
            float sn = sqrtf(fmaxf(1.f - cc * cc, 0.f));
            logit = ARC_S * (cc * COS_M - sn * SIN_M);
            g_lab[gi] = logit;
        } else {
            logit = ARC_S * cm;
        }
        lse_merge(M, S, logit, 1.f);
    }
    float pM = __shfl_xor_sync(0xffffffffu, M, 1);
    float pS = __shfl_xor_sync(0xffffffffu, S, 1);
    lse_merge(M, S, pM, pS);
    if (h == 0) {
        g_arc_m[gi * NTILES_G + tileN] = M;
        g_arc_s[gi * NTILES_G + tileN] = S;
    }
}

__global__ void k_arc_reduce() {
    int row = blockIdx.x, tid = threadIdx.x;
    float M = -1e30f, S = 0.f;
    for (int t = tid; t < NTILES_G; t += 256)
        lse_merge(M, S, g_arc_m[row * NTILES_G + t], g_arc_s[row * NTILES_G + t]);
    __shared__ float sm[256], ss[256];
    sm[tid] = M; ss[tid] = S;
    __syncthreads();
    for (int st = 128; st > 0; st >>= 1) {
        if (tid < st) {
            float m1 = sm[tid], s1 = ss[tid];
            lse_merge(m1, s1, sm[tid + st], ss[tid + st]);
            sm[tid] = m1; ss[tid] = s1;
        }
        __syncthreads();
    }
    if (tid == 0) {
        float lse = sm[0] + logf(ss[0]);
        atomicAdd(&g_arc_sum, (double)(lse - g_lab[row]));
    }
}

// ============================================================================
// sim GEMM: 128x128 tile, same machinery, fused triplet epilogue (register-level)
// Stage: A_hi 10240, A_lo 10240, B_hi 10240, B_lo 10240 -> 40960; labels at +81920
// ============================================================================
#define S_OFF_AL 10240
#define S_OFF_BH 20480
#define S_OFF_BL 30720
#define S_STG    40960
#define S_SMEM   (2 * S_STG + 512)

__device__ __forceinline__ void load_sim_stage(uint32_t st, int kc, int rowA, int colB, int tid) {
    int gk = kc * 32;
    #pragma unroll
    for (int i = 0; i < 2; i++) {
        int idx = tid + i * 256;
        int row = idx >> 2, c = idx & 3;
        uint32_t so = row * 80 + c * 16;
        cp16(st + so,            &g_e_hi[(rowA + row) * D_DIM + gk + c * 8]);
        cp16(st + S_OFF_AL + so, &g_e_lo[(rowA + row) * D_DIM + gk + c * 8]);
        cp16(st + S_OFF_BH + so, &g_e_hi[(colB + row) * D_DIM + gk + c * 8]);
        cp16(st + S_OFF_BL + so, &g_e_lo[(colB + row) * D_DIM + gk + c * 8]);
    }
}

__global__ void __launch_bounds__(256, 1) k_gemm_sim(const int* __restrict__ labels) {
    extern __shared__ char smem[];
    uint32_t sb = smem_u32(smem);
    int tid = threadIdx.x, wid = tid >> 5, lane = tid & 31;
    int warpM = wid & 3, warpN = wid >> 2;          // 4M x 2N
    int rowA = blockIdx.x * 128;
    int colB = blockIdx.y * 128;

    int* slab = (int*)(smem + 2 * S_STG);
    if (tid < 128) slab[tid] = labels[colB + tid];

    float acc[2][8][4];
    #pragma unroll
    for (int a = 0; a < 2; a++)
        #pragma unroll
        for (int b = 0; b < 8; b++)
            #pragma unroll
            for (int c = 0; c < 4; c++) acc[a][b][c] = 0.f;

    int lrow = lane & 15, lhalf = lane >> 4;
    uint32_t aoff[2], boff[4];
    #pragma unroll
    for (int mt = 0; mt < 2; mt++) aoff[mt] = (warpM * 32 + mt * 16 + lrow) * 80 + lhalf * 16;
    #pragma unroll
    for (int bt = 0; bt < 4; bt++) boff[bt] = (warpN * 64 + bt * 16 + lrow) * 80 + lhalf * 16;

    load_sim_stage(sb, 0, rowA, colB, tid); CP_COMMIT();
    load_sim_stage(sb + S_STG, 1, rowA, colB, tid); CP_COMMIT();

    for (int kc = 0; kc < 16; kc++) {
        if (kc < 15) CP_WAIT1(); else CP_WAIT0();
        __syncthreads();
        uint32_t st = sb + (kc & 1) * S_STG;
        #pragma unroll
        for (int ks = 0; ks < 2; ks++) {
            uint32_t ah[2][4], al[2][4], bh[4][4], bl[4][4];
            #pragma unroll
            for (int mt = 0; mt < 2; mt++) {
                ldsm4(ah[mt], st + aoff[mt] + ks * 32);
                ldsm4(al[mt], st + S_OFF_AL + aoff[mt] + ks * 32);
            }
            #pragma unroll
            for (int bt = 0; bt < 4; bt++) {
                ldsm4(bh[bt], st + S_OFF_BH + boff[bt] + ks * 32);
                ldsm4(bl[bt], st + S_OFF_BL + boff[bt] + ks * 32);
            }
            #pragma unroll
            for (int mt = 0; mt < 2; mt++)
                #pragma unroll
                for (int nt = 0; nt < 8; nt++) {
                    int bt = nt >> 1, sel = nt & 1;
                    mma16816(acc[mt][nt], ah[mt], bh[bt][sel], bh[bt][sel | 2]);
                    mma16816(acc[mt][nt], ah[mt], bl[bt][sel], bl[bt][sel | 2]);
                    mma16816(acc[mt][nt], al[mt], bh[bt][sel], bh[bt][sel | 2]);
                }
        }
        __syncthreads();
        if (kc + 2 < 16) { load_sim_stage(sb + (kc & 1) * S_STG, kc + 2, rowA, colB, tid); CP_COMMIT(); }
    }

    // ---- fused triplet epilogue: per-thread local, quad-shfl reduce, atomics ----
    #pragma unroll
    for (int mt = 0; mt < 2; mt++) {
        #pragma unroll
        for (int ro = 0; ro < 2; ro++) {
            int r = warpM * 32 + mt * 16 + (lane >> 2) + ro * 8;
            int gi = rowA + r;
            int myl = __ldg(&labels[gi]);
            float dap = -1.f, dan = 3.f;
            #pragma unroll
            for (int nt = 0; nt < 8; nt++) {
                #pragma unroll
                for (int j = 0; j < 2; j++) {
                    int cl = warpN * 64 + nt * 8 + ((lane & 3) << 1) + j;
                    int gj = colB + cl;
                    float sim  = acc[mt][nt][ro * 2 + j];
                    float dist = sqrtf(fmaxf(2.f - 2.f * sim, 0.f));
                    if (slab[cl] == myl) { if (gj != gi) dap = fmaxf(dap, dist); }
                    else                 { dan = fminf(dan, dist); }
                }
            }
            #pragma unroll
            for (int off = 1; off < 4; off <<= 1) {
                dap = fmaxf(dap, __shfl_xor_sync(0xffffffffu, dap, off));
                dan = fminf(dan, __shfl_xor_sync(0xffffffffu, dan, off));
            }
            if ((lane & 3) == 0) {
                atomicMax(&g_dap[gi], __float_as_int(dap));
                atomicMin(&g_dan[gi], __float_as_int(dan));
            }
        }
    }
}

__global__ void k_trip_final() {
    int i = blockIdx.x * blockDim.x + threadIdx.x;
    if (i >= N_SAMP) return;
    float dap = __int_as_float(g_dap[i]);
    float dan = __int_as_float(g_dan[i]);
    bool valid = (dap >= 0.f) && (dan < 2.5f);
    float tl = valid ? fmaxf(dap - dan + TRIP_M, 0.f) : 0.f;
    if (tl > 0.f) {
        atomicAdd(&g_tl_sum, (double)tl);
        atomicAdd(&g_nnz, 1);
    }
}

__global__ void k_center(const int* __restrict__ labels, const float* __restrict__ centers) {
    int row = blockIdx.x, tid = threadIdx.x;
    int lab = labels[row];
    const float* c = centers + lab * D_DIM;
    const float* e = g_e + row * D_DIM;
    float s = 0.f;
    for (int d = tid; d < D_DIM; d += 256) { float diff = e[d] - c[d]; s += diff * diff; }
    __shared__ float red[256];
    red[tid] = s; __syncthreads();
    for (int st = 128; st > 0; st >>= 1) { if (tid < st) red[tid] += red[tid + st]; __syncthreads(); }
    if (tid == 0) atomicAdd(&g_center_sum, (double)red[0]);
}

__global__ void k_final(float* __restrict__ out) {
    double arc  = g_arc_sum / (double)N_SAMP;
    int    nnz  = g_nnz > 1 ? g_nnz : 1;
    double trip = g_tl_sum / (double)nnz;
    double cen  = g_center_sum / (double)N_SAMP;
    out[0] = (float)(arc + 0.5 * trip + 0.01 * cen);
}

// ---------------- launch ----------------
extern "C" void kernel_launch(void* const* d_in, const int* in_sizes, int n_in,
                              void* d_out, int out_size) {
    const float* emb     = (const float*)d_in[0];
    const int*   labels  = (const int*)  d_in[1];
    const float* W       = (const float*)d_in[2];
    const float* centers = (const float*)d_in[3];
    float* out = (float*)d_out;

    static int attr_done = 0;
    cudaFuncSetAttribute(k_gemm_arc, cudaFuncAttributeMaxDynamicSharedMemorySize, A_SMEM);
    cudaFuncSetAttribute(k_gemm_sim, cudaFuncAttributeMaxDynamicSharedMemorySize, S_SMEM);
    (void)attr_done;

    k_init<<<2, 1024>>>();
    k_norm_emb<<<N_SAMP, 256>>>(emb);
    k_wnorm<<<(CK + 255) / 256, 256>>>(W);
    k_wtrans<<<dim3((CK + 31) / 32, D_DIM / 32), dim3(32, 8)>>>(W);

    k_gemm_arc<<<dim3(16, NTILES_G), 256, A_SMEM>>>(labels);
    k_arc_reduce<<<N_SAMP, 256>>>();

    k_gemm_sim<<<dim3(16, 16), 256, S_SMEM>>>(labels);
    k_trip_final<<<8, 256>>>();

    k_center<<<N_SAMP, 256>>>(labels, centers);
    k_final<<<1, 1>>>(out);
}